// round 1
// baseline (speedup 1.0000x reference)
#include <cuda_runtime.h>

#define NB 8
#define NT 2048
#define NC 1024
#define NH 64

// scratch for projections (allocation-free rule: __device__ globals)
__device__ float g_q[NB * NT * NH];
__device__ float g_k[NB * NT * NH];
__device__ float g_v[NB * NT * NH];

// ---------------------------------------------------------------------------
// Projection: out[t][h] = sum_c x[t][c] * W[h][c]
// grid (128, 3): 128 token tiles of 128, y selects (Wk->g_k, Wq->g_q, Wv->g_v)
// block 256 threads = 16x16; each thread: 8 tokens x 4 outputs
// ---------------------------------------------------------------------------
__global__ __launch_bounds__(256) void proj_kernel(
    const float* __restrict__ x, const float* __restrict__ Wk,
    const float* __restrict__ Wq, const float* __restrict__ Wv)
{
    __shared__ float xs[128][33];   // pad 33: conflict-free scalar access
    __shared__ float wsT[32][64];   // transposed W chunk: wsT[c][o]

    const float* __restrict__ W;
    float* out;
    if (blockIdx.y == 0)      { W = Wk; out = g_k; }
    else if (blockIdx.y == 1) { W = Wq; out = g_q; }
    else                      { W = Wv; out = g_v; }

    const int tid = threadIdx.x;
    const int tx = tid & 15, ty = tid >> 4;
    const int t0 = ty * 8;
    const int o0 = tx * 4;
    const long tile = (long)blockIdx.x * 128;

    float acc[8][4];
#pragma unroll
    for (int i = 0; i < 8; i++)
#pragma unroll
        for (int j = 0; j < 4; j++) acc[i][j] = 0.f;

    for (int cc = 0; cc < NC; cc += 32) {
        // load x tile [128 tokens x 32 c]
#pragma unroll
        for (int k = 0; k < 4; k++) {
            int f4 = tid + 256 * k;
            int token = f4 >> 3, c4 = f4 & 7;
            float4 v = *(const float4*)(x + (tile + token) * NC + cc + c4 * 4);
            xs[token][c4 * 4 + 0] = v.x;
            xs[token][c4 * 4 + 1] = v.y;
            xs[token][c4 * 4 + 2] = v.z;
            xs[token][c4 * 4 + 3] = v.w;
        }
        // load W chunk transposed [32 c x 64 o]
#pragma unroll
        for (int k = 0; k < 2; k++) {
            int f4 = tid + 256 * k;
            int o = f4 >> 3, k4 = f4 & 7;
            float4 v = *(const float4*)(W + (long)o * NC + cc + k4 * 4);
            wsT[k4 * 4 + 0][o] = v.x;
            wsT[k4 * 4 + 1][o] = v.y;
            wsT[k4 * 4 + 2][o] = v.z;
            wsT[k4 * 4 + 3][o] = v.w;
        }
        __syncthreads();

#pragma unroll
        for (int kk = 0; kk < 32; kk++) {
            float4 wf = *(const float4*)&wsT[kk][o0];
            float xv[8];
#pragma unroll
            for (int i = 0; i < 8; i++) xv[i] = xs[t0 + i][kk];
#pragma unroll
            for (int i = 0; i < 8; i++) {
                acc[i][0] += xv[i] * wf.x;
                acc[i][1] += xv[i] * wf.y;
                acc[i][2] += xv[i] * wf.z;
                acc[i][3] += xv[i] * wf.w;
            }
        }
        __syncthreads();
    }

#pragma unroll
    for (int i = 0; i < 8; i++) {
        float4 v = make_float4(acc[i][0], acc[i][1], acc[i][2], acc[i][3]);
        *(float4*)(out + (tile + t0 + i) * NH + o0) = v;
    }
}

// ---------------------------------------------------------------------------
// Flash attention, causal. Tq = Tk = 64. 256 threads (16x16), 4x4 reg tiles.
// smem (dynamic, 50176 B):
//   Qt  [64h][64r]  (transposed -> conflict-free float4 reads)
//   KV  [64h][64c] as K-transposed, then reused as V [64s][64o]
//   S   [64r][65]   (pad 65 -> conflict-free softmax scan + PV broadcast reads)
//   mrow/lrow/frow [64] each
// Each block handles q-tile pair (i, 31-i) => 33 tiles/block (balanced).
// ---------------------------------------------------------------------------
__global__ __launch_bounds__(256) void attn_kernel(float* __restrict__ out)
{
    extern __shared__ float sm[];
    float* Qt = sm;                 // 4096
    float* KV = sm + 4096;          // 4096
    float* S  = sm + 8192;          // 64*65 = 4160
    float* mrow = sm + 8192 + 4160; // 64
    float* lrow = mrow + 64;        // 64
    float* frow = lrow + 64;        // 64

    const int tid = threadIdx.x;
    const int tx = tid & 15, ty = tid >> 4;
    const int r0 = ty * 4, c0 = tx * 4;
    const int b = blockIdx.y;
    const float scale = 0.125f;     // HS^-0.5

#pragma unroll 1
    for (int pass = 0; pass < 2; pass++) {
        const int qt = pass ? (31 - (int)blockIdx.x) : (int)blockIdx.x;
        const float* qg = g_q + ((long)b * NT + qt * 64) * 64;

        // load Q tile transposed: Qt[h][r]
#pragma unroll
        for (int k = 0; k < 4; k++) {
            int f4 = tid + 256 * k;
            int r = f4 >> 4, h4 = f4 & 15;
            float4 v = *(const float4*)(qg + r * 64 + h4 * 4);
            Qt[(h4 * 4 + 0) * 64 + r] = v.x;
            Qt[(h4 * 4 + 1) * 64 + r] = v.y;
            Qt[(h4 * 4 + 2) * 64 + r] = v.z;
            Qt[(h4 * 4 + 3) * 64 + r] = v.w;
        }
        if (tid < 64) { mrow[tid] = -1e30f; lrow[tid] = 0.f; }

        float O[4][4];
#pragma unroll
        for (int i = 0; i < 4; i++)
#pragma unroll
            for (int j = 0; j < 4; j++) O[i][j] = 0.f;

        __syncthreads();

        for (int kt = 0; kt <= qt; kt++) {
            // load K tile transposed: KV[h][c]
            const float* kg = g_k + ((long)b * NT + kt * 64) * 64;
#pragma unroll
            for (int k = 0; k < 4; k++) {
                int f4 = tid + 256 * k;
                int c = f4 >> 4, h4 = f4 & 15;
                float4 v = *(const float4*)(kg + c * 64 + h4 * 4);
                KV[(h4 * 4 + 0) * 64 + c] = v.x;
                KV[(h4 * 4 + 1) * 64 + c] = v.y;
                KV[(h4 * 4 + 2) * 64 + c] = v.z;
                KV[(h4 * 4 + 3) * 64 + c] = v.w;
            }
            __syncthreads();

            // S = Q K^T   (4x4 per thread)
            float sa[4][4];
#pragma unroll
            for (int i = 0; i < 4; i++)
#pragma unroll
                for (int j = 0; j < 4; j++) sa[i][j] = 0.f;

#pragma unroll 8
            for (int h = 0; h < 64; h++) {
                float4 qf = *(const float4*)(Qt + h * 64 + r0);
                float4 kf = *(const float4*)(KV + h * 64 + c0);
                sa[0][0] += qf.x * kf.x; sa[0][1] += qf.x * kf.y;
                sa[0][2] += qf.x * kf.z; sa[0][3] += qf.x * kf.w;
                sa[1][0] += qf.y * kf.x; sa[1][1] += qf.y * kf.y;
                sa[1][2] += qf.y * kf.z; sa[1][3] += qf.y * kf.w;
                sa[2][0] += qf.z * kf.x; sa[2][1] += qf.z * kf.y;
                sa[2][2] += qf.z * kf.z; sa[2][3] += qf.z * kf.w;
                sa[3][0] += qf.w * kf.x; sa[3][1] += qf.w * kf.y;
                sa[3][2] += qf.w * kf.z; sa[3][3] += qf.w * kf.w;
            }
#pragma unroll
            for (int i = 0; i < 4; i++)
#pragma unroll
                for (int j = 0; j < 4; j++)
                    S[(r0 + i) * 65 + c0 + j] = sa[i][j];
            __syncthreads();

            // overwrite KV with V tile (natural layout [s][o]) — all threads
            const float4* vg = (const float4*)(g_v + ((long)b * NT + kt * 64) * 64);
#pragma unroll
            for (int k = 0; k < 4; k++)
                ((float4*)KV)[tid + 256 * k] = vg[tid + 256 * k];

            // online softmax on rows (threads 0..63), concurrent with V load
            if (tid < 64) {
                const int r = tid;
                const int cmax = (kt == qt) ? (r + 1) : 64;
                float* Sr = S + r * 65;
                float mold = mrow[r];
                float mt = mold;
                for (int c = 0; c < cmax; c++)
                    mt = fmaxf(mt, Sr[c] * scale);
                float f = __expf(mold - mt);
                float l = lrow[r] * f;
#pragma unroll 8
                for (int c = 0; c < 64; c++) {
                    float p = (c < cmax) ? __expf(Sr[c] * scale - mt) : 0.f;
                    Sr[c] = p;
                    l += p;
                }
                mrow[r] = mt; lrow[r] = l; frow[r] = f;
            }
            __syncthreads();

            // rescale O and accumulate O += P V
            float fi[4];
#pragma unroll
            for (int i = 0; i < 4; i++) fi[i] = frow[r0 + i];
#pragma unroll
            for (int i = 0; i < 4; i++)
#pragma unroll
                for (int j = 0; j < 4; j++) O[i][j] *= fi[i];

#pragma unroll 8
            for (int s = 0; s < 64; s++) {
                float4 vf = *(const float4*)(KV + s * 64 + c0);
                float p0 = S[(r0 + 0) * 65 + s];
                float p1 = S[(r0 + 1) * 65 + s];
                float p2 = S[(r0 + 2) * 65 + s];
                float p3 = S[(r0 + 3) * 65 + s];
                O[0][0] += p0 * vf.x; O[0][1] += p0 * vf.y;
                O[0][2] += p0 * vf.z; O[0][3] += p0 * vf.w;
                O[1][0] += p1 * vf.x; O[1][1] += p1 * vf.y;
                O[1][2] += p1 * vf.z; O[1][3] += p1 * vf.w;
                O[2][0] += p2 * vf.x; O[2][1] += p2 * vf.y;
                O[2][2] += p2 * vf.z; O[2][3] += p2 * vf.w;
                O[3][0] += p3 * vf.x; O[3][1] += p3 * vf.y;
                O[3][2] += p3 * vf.z; O[3][3] += p3 * vf.w;
            }
            __syncthreads();
        }

        // normalize and write output
#pragma unroll
        for (int i = 0; i < 4; i++) {
            float inv = 1.0f / lrow[r0 + i];
            float4 v = make_float4(O[i][0] * inv, O[i][1] * inv,
                                   O[i][2] * inv, O[i][3] * inv);
            *(float4*)(out + ((long)b * NT + qt * 64 + r0 + i) * 64 + c0) = v;
        }
        __syncthreads();   // protect smem before second pass reuses it
    }
}

extern "C" void kernel_launch(void* const* d_in, const int* in_sizes, int n_in,
                              void* d_out, int out_size)
{
    const float* x  = (const float*)d_in[0];
    const float* Wk = (const float*)d_in[1];
    const float* Wq = (const float*)d_in[2];
    const float* Wv = (const float*)d_in[3];
    float* out = (float*)d_out;

    proj_kernel<<<dim3(128, 3), 256>>>(x, Wk, Wq, Wv);

    const int smem_bytes = (4096 + 4096 + 64 * 65 + 192) * 4;  // 50176
    cudaFuncSetAttribute(attn_kernel,
                         cudaFuncAttributeMaxDynamicSharedMemorySize, smem_bytes);
    attn_kernel<<<dim3(16, 8), 256, smem_bytes>>>(out);
}